// round 6
// baseline (speedup 1.0000x reference)
#include <cuda_runtime.h>
#include <cstdint>

// Persistent 2-stage TMA pipeline. 296 CTAs (2/SM), each loops over tiles of
// 1024 rows. Double-buffered: load(i+2) overlaps compute/store(i).
// smem: 2x36KB in + 2x12KB out + 2 mbarriers = ~96KB dynamic.

constexpr int TPB = 256;
constexpr int RPT = 4;
constexpr int RPB = TPB * RPT;            // 1024 rows per tile
constexpr int IN4_T  = RPB * 9 / 4;       // 2304 float4
constexpr int OUT4_T = RPB * 3 / 4;       // 768 float4
constexpr int IN_BYTES  = IN4_T * 16;     // 36864
constexpr int OUT_BYTES = OUT4_T * 16;    // 12288
constexpr int SMEM_DYN = (2 * IN4_T + 2 * OUT4_T) * 16 + 16;  // + mbarriers
constexpr int GRID = 296;                 // 2 per SM x 148 SMs

__device__ __forceinline__ void process_row(const float* __restrict__ x,
                                            float* __restrict__ o)
{
    int mi[3];
#pragma unroll
    for (int j = 0; j < 3; j++) {
        float a0 = x[3*j], a1 = x[3*j+1], a2 = x[3*j+2];
        bool q0 = (a0 > a1) && (a0 > a2);
        bool q2 = (a2 > a0) && (a2 > a1);
        mi[j] = (int)q0 - (int)q2;
    }
    int calc = ((mi[1] < 0) ? -mi[1] : mi[1]) * (mi[0] + mi[1] + mi[2]);
    int sc   = (calc > 0) - (calc < 0);

    float m[9];
#pragma unroll
    for (int j = 0; j < 3; j++) {
        bool keep = (mi[j] == sc);
#pragma unroll
        for (int k = 0; k < 3; k++)
            m[3*j + k] = keep ? x[3*j + k] : 0.0f;
    }
    float v0, v1, v2;
    if (sc == 0)      { v0 = m[1]; v1 = m[4]; v2 = m[7]; }
    else if (sc > 0)  { v0 = m[0]; v1 = m[3]; v2 = m[6]; }
    else              { v0 = m[2]; v1 = m[5]; v2 = m[8]; }

    bool b1 = (v1 > v0);
    float best01 = b1 ? v1 : v0;
    bool b2 = (v2 > best01);
#pragma unroll
    for (int k = 0; k < 3; k++) {
        float t01 = b1 ? m[3 + k] : m[k];
        o[k] = b2 ? m[6 + k] : t01;
    }
}

__device__ __forceinline__ void mbar_wait(uint32_t mb, int phase)
{
    uint32_t done;
    do {
        asm volatile(
            "{\n\t.reg .pred p;\n\t"
            "mbarrier.try_wait.parity.shared.b64 p, [%1], %2;\n\t"
            "selp.b32 %0, 1, 0, p;\n\t}"
            : "=r"(done) : "r"(mb), "r"(phase) : "memory");
    } while (!done);
}

__global__ void __launch_bounds__(TPB) concat_pipe(
    const float4* __restrict__ in4, float4* __restrict__ out4, int n_tiles)
{
    extern __shared__ float4 smem[];
    float4* in_buf  = smem;                          // [2][IN4_T]
    float4* out_buf = smem + 2 * IN4_T;              // [2][OUT4_T]
    uint64_t* mbar  = (uint64_t*)(out_buf + 2 * OUT4_T);  // [2]

    const int tid = threadIdx.x;
    const int G = gridDim.x;
    uint32_t mb[2];
    mb[0] = (uint32_t)__cvta_generic_to_shared(&mbar[0]);
    mb[1] = mb[0] + 8;
    uint32_t in_s[2], out_s[2];
    in_s[0]  = (uint32_t)__cvta_generic_to_shared(in_buf);
    in_s[1]  = in_s[0] + IN_BYTES;
    out_s[0] = (uint32_t)__cvta_generic_to_shared(out_buf);
    out_s[1] = out_s[0] + OUT_BYTES;

    if (tid == 0) {
        asm volatile("mbarrier.init.shared.b64 [%0], 1;" :: "r"(mb[0]) : "memory");
        asm volatile("mbarrier.init.shared.b64 [%0], 1;" :: "r"(mb[1]) : "memory");
    }
    __syncthreads();

    const int first = blockIdx.x;
    const int count = (n_tiles > first) ? (n_tiles - first + G - 1) / G : 0;

    // Prologue: prefetch tiles 0 and 1 of this CTA's sequence
    if (tid == 0) {
#pragma unroll
        for (int k = 0; k < 2; k++) {
            if (k < count) {
                const float4* src = in4 + (size_t)(first + k * G) * IN4_T;
                asm volatile("mbarrier.arrive.expect_tx.shared.b64 _, [%0], %1;"
                             :: "r"(mb[k]), "r"(IN_BYTES) : "memory");
                asm volatile(
                    "cp.async.bulk.shared::cta.global.mbarrier::complete_tx::bytes "
                    "[%0], [%1], %2, [%3];"
                    :: "r"(in_s[k]), "l"(src), "r"(IN_BYTES), "r"(mb[k]) : "memory");
            }
        }
    }

    int ph0 = 0, ph1 = 0;

    for (int i = 0; i < count; i++) {
        const int s = i & 1;
        const size_t tile = (size_t)(first + i * G);

        // Wait for this buffer's load (prefetched 2 iterations ago)
        if (s == 0) { mbar_wait(mb[0], ph0); ph0 ^= 1; }
        else        { mbar_wait(mb[1], ph1); ph1 ^= 1; }

        // Pull 4 rows: 9 LDS.128 @144B lane stride (conflict-free)
        float x[36];
        const float4* ib = in_buf + s * IN4_T + tid * 9;
#pragma unroll
        for (int k = 0; k < 9; k++) {
            float4 v = ib[k];
            x[4*k+0] = v.x; x[4*k+1] = v.y; x[4*k+2] = v.z; x[4*k+3] = v.w;
        }

        // out_buf[s] reuse: store from iteration i-2 must have drained reads
        if (tid == 0 && i >= 2)
            asm volatile("cp.async.bulk.wait_group.read 1;" ::: "memory");
        __syncthreads();  // all LDS done + out_buf[s] free, block-wide

        // Prefetch tile i+2 into in_buf[s]
        if (tid == 0 && i + 2 < count) {
            const float4* src = in4 + (size_t)(first + (i + 2) * G) * IN4_T;
            asm volatile("mbarrier.arrive.expect_tx.shared.b64 _, [%0], %1;"
                         :: "r"(mb[s]), "r"(IN_BYTES) : "memory");
            asm volatile(
                "cp.async.bulk.shared::cta.global.mbarrier::complete_tx::bytes "
                "[%0], [%1], %2, [%3];"
                :: "r"(in_s[s]), "l"(src), "r"(IN_BYTES), "r"(mb[s]) : "memory");
        }

        float o[12];
#pragma unroll
        for (int r = 0; r < RPT; r++)
            process_row(x + 9*r, o + 3*r);

        // Stage output: 3 STS.128 @48B stride (conflict-free)
        float4* ob = out_buf + s * OUT4_T + tid * 3;
#pragma unroll
        for (int k = 0; k < 3; k++) {
            float4 v;
            v.x = o[4*k+0]; v.y = o[4*k+1]; v.z = o[4*k+2]; v.w = o[4*k+3];
            ob[k] = v;
        }
        __syncthreads();

        // Fire-and-forget bulk store
        if (tid == 0) {
            float4* dst = out4 + tile * OUT4_T;
            asm volatile("fence.proxy.async.shared::cta;" ::: "memory");
            asm volatile(
                "cp.async.bulk.global.shared::cta.bulk_group [%0], [%1], %2;"
                :: "l"(dst), "r"(out_s[s]), "r"(OUT_BYTES) : "memory");
            asm volatile("cp.async.bulk.commit_group;" ::: "memory");
        }
    }

    // Drain outstanding stores before exit
    if (tid == 0 && count > 0)
        asm volatile("cp.async.bulk.wait_group 0;" ::: "memory");
}

// Scalar tail for n_rows % 1024 != 0 (not hit for N = 2^23)
__global__ void concat_tail(const float* __restrict__ in,
                            float* __restrict__ out,
                            int row_start, int n_rows)
{
    int row = row_start + blockIdx.x * blockDim.x + threadIdx.x;
    if (row >= n_rows) return;
    float x[9];
#pragma unroll
    for (int k = 0; k < 9; k++) x[k] = in[(size_t)row * 9 + k];
    float o[3];
    process_row(x, o);
#pragma unroll
    for (int k = 0; k < 3; k++) out[(size_t)row * 3 + k] = o[k];
}

extern "C" void kernel_launch(void* const* d_in, const int* in_sizes, int n_in,
                              void* d_out, int out_size)
{
    const float* in = (const float*)d_in[0];
    float* out = (float*)d_out;
    int n_rows = in_sizes[0] / 9;

    static bool attr_set = false;
    if (!attr_set) {
        cudaFuncSetAttribute(concat_pipe,
                             cudaFuncAttributeMaxDynamicSharedMemorySize,
                             SMEM_DYN);
        attr_set = true;
    }

    int n_tiles = n_rows / RPB;
    if (n_tiles > 0) {
        int grid = (n_tiles < GRID) ? n_tiles : GRID;
        concat_pipe<<<grid, TPB, SMEM_DYN>>>((const float4*)in, (float4*)out,
                                             n_tiles);
    }
    int done = n_tiles * RPB;
    int rem = n_rows - done;
    if (rem > 0) {
        int grid = (rem + 255) / 256;
        concat_tail<<<grid, 256>>>(in, out, done, n_rows);
    }
}

// round 7
// speedup vs baseline: 1.0943x; 1.0943x over previous
#include <cuda_runtime.h>
#include <cstdint>

// 256 rows per 256-thread block, 1 row/thread. 9 KB smem staged via cp.async
// (L1-bypass), buffer reused for the 3 KB output. Tiny blocks + low regs
// -> 8 CTAs/SM (100% occ): latency hiding via many independent CTAs.

constexpr int TPB = 256;
constexpr int RPB = 256;                  // rows per block
constexpr int IN4 = RPB * 9 / 4;          // 576 float4 = 9 KB
constexpr int OUT4 = RPB * 3 / 4;         // 192 float4 = 3 KB (reuses buffer)

__device__ __forceinline__ void process_row(const float* __restrict__ x,
                                            float* __restrict__ o)
{
    int mi[3];
#pragma unroll
    for (int j = 0; j < 3; j++) {
        float a0 = x[3*j], a1 = x[3*j+1], a2 = x[3*j+2];
        bool q0 = (a0 > a1) && (a0 > a2);
        bool q2 = (a2 > a0) && (a2 > a1);
        mi[j] = (int)q0 - (int)q2;
    }
    int calc = ((mi[1] < 0) ? -mi[1] : mi[1]) * (mi[0] + mi[1] + mi[2]);
    int sc   = (calc > 0) - (calc < 0);

    float m[9];
#pragma unroll
    for (int j = 0; j < 3; j++) {
        bool keep = (mi[j] == sc);
#pragma unroll
        for (int k = 0; k < 3; k++)
            m[3*j + k] = keep ? x[3*j + k] : 0.0f;
    }
    float v0, v1, v2;
    if (sc == 0)      { v0 = m[1]; v1 = m[4]; v2 = m[7]; }
    else if (sc > 0)  { v0 = m[0]; v1 = m[3]; v2 = m[6]; }
    else              { v0 = m[2]; v1 = m[5]; v2 = m[8]; }

    bool b1 = (v1 > v0);
    float best01 = b1 ? v1 : v0;
    bool b2 = (v2 > best01);
#pragma unroll
    for (int k = 0; k < 3; k++) {
        float t01 = b1 ? m[3 + k] : m[k];
        o[k] = b2 ? m[6 + k] : t01;
    }
}

__global__ void __launch_bounds__(TPB, 8) concat_small(
    const float4* __restrict__ in4, float4* __restrict__ out4)
{
    __shared__ float4 s[IN4];             // 9 KB, reused for output
    float* sf = reinterpret_cast<float*>(s);

    const int tid = threadIdx.x;
    const size_t base = (size_t)blockIdx.x * IN4;

    // Stage 576 float4 via cp.async.cg: 2 full rounds + 64-thread remainder
#pragma unroll
    for (int i = 0; i < 2; i++) {
        uint32_t dst = (uint32_t)__cvta_generic_to_shared(&s[i * TPB + tid]);
        const float4* src = in4 + base + i * TPB + tid;
        asm volatile("cp.async.cg.shared.global [%0], [%1], 16;"
                     :: "r"(dst), "l"(src) : "memory");
    }
    if (tid < IN4 - 2 * TPB) {            // 64 threads
        uint32_t dst = (uint32_t)__cvta_generic_to_shared(&s[2 * TPB + tid]);
        const float4* src = in4 + base + 2 * TPB + tid;
        asm volatile("cp.async.cg.shared.global [%0], [%1], 16;"
                     :: "r"(dst), "l"(src) : "memory");
    }
    asm volatile("cp.async.commit_group;" ::: "memory");
    asm volatile("cp.async.wait_group 0;" ::: "memory");
    __syncthreads();

    // 9 x LDS.32 at stride 9 floats: gcd(9,32)=1 -> conflict-free
    float x[9];
#pragma unroll
    for (int k = 0; k < 9; k++) x[k] = sf[tid * 9 + k];
    __syncthreads();                      // reads done before buffer reuse

    float o[3];
    process_row(x, o);

    // 3 x STS.32 at stride 3 floats: conflict-free
#pragma unroll
    for (int k = 0; k < 3; k++) sf[tid * 3 + k] = o[k];
    __syncthreads();

    // Coalesced output: 192 float4
    if (tid < OUT4)
        out4[(size_t)blockIdx.x * OUT4 + tid] = s[tid];
}

// Scalar tail for n_rows % 256 != 0 (not hit for N = 2^23)
__global__ void concat_tail(const float* __restrict__ in,
                            float* __restrict__ out,
                            int row_start, int n_rows)
{
    int row = row_start + blockIdx.x * blockDim.x + threadIdx.x;
    if (row >= n_rows) return;
    float x[9];
#pragma unroll
    for (int k = 0; k < 9; k++) x[k] = in[(size_t)row * 9 + k];
    float o[3];
    process_row(x, o);
#pragma unroll
    for (int k = 0; k < 3; k++) out[(size_t)row * 3 + k] = o[k];
}

extern "C" void kernel_launch(void* const* d_in, const int* in_sizes, int n_in,
                              void* d_out, int out_size)
{
    const float* in = (const float*)d_in[0];
    float* out = (float*)d_out;
    int n_rows = in_sizes[0] / 9;

    int nfull = n_rows / RPB;
    if (nfull > 0)
        concat_small<<<nfull, TPB>>>((const float4*)in, (float4*)out);

    int done = nfull * RPB;
    int rem = n_rows - done;
    if (rem > 0) {
        int grid = (rem + 255) / 256;
        concat_tail<<<grid, 256>>>(in, out, done, n_rows);
    }
}

// round 8
// speedup vs baseline: 1.0999x; 1.0052x over previous
#include <cuda_runtime.h>
#include <cstdint>

// 512 rows per 256-thread block, 2 rows/thread. 18 KB smem via cp.async.cg,
// buffer reused for 6 KB output. Targets 8 CTAs/SM (100% occ) with the
// staging overhead amortized over 2 rows. All smem ops 64-bit, conflict-free.

constexpr int TPB = 256;
constexpr int RPB = 512;                  // rows per block
constexpr int IN4 = RPB * 9 / 4;          // 1152 float4 = 18 KB
constexpr int OUT4 = RPB * 3 / 4;         // 384 float4 = 6 KB (reuses buffer)

__device__ __forceinline__ void process_row(const float* __restrict__ x,
                                            float* __restrict__ o)
{
    int mi[3];
#pragma unroll
    for (int j = 0; j < 3; j++) {
        float a0 = x[3*j], a1 = x[3*j+1], a2 = x[3*j+2];
        bool q0 = (a0 > a1) && (a0 > a2);
        bool q2 = (a2 > a0) && (a2 > a1);
        mi[j] = (int)q0 - (int)q2;
    }
    int calc = ((mi[1] < 0) ? -mi[1] : mi[1]) * (mi[0] + mi[1] + mi[2]);
    int sc   = (calc > 0) - (calc < 0);

    float m[9];
#pragma unroll
    for (int j = 0; j < 3; j++) {
        bool keep = (mi[j] == sc);
#pragma unroll
        for (int k = 0; k < 3; k++)
            m[3*j + k] = keep ? x[3*j + k] : 0.0f;
    }
    float v0, v1, v2;
    if (sc == 0)      { v0 = m[1]; v1 = m[4]; v2 = m[7]; }
    else if (sc > 0)  { v0 = m[0]; v1 = m[3]; v2 = m[6]; }
    else              { v0 = m[2]; v1 = m[5]; v2 = m[8]; }

    bool b1 = (v1 > v0);
    float best01 = b1 ? v1 : v0;
    bool b2 = (v2 > best01);
#pragma unroll
    for (int k = 0; k < 3; k++) {
        float t01 = b1 ? m[3 + k] : m[k];
        o[k] = b2 ? m[6 + k] : t01;
    }
}

__global__ void __launch_bounds__(TPB, 8) concat_r2(
    const float4* __restrict__ in4, float4* __restrict__ out4)
{
    __shared__ float4 s[IN4];             // 18 KB, reused for output
    float2* sf2 = reinterpret_cast<float2*>(s);

    const int tid = threadIdx.x;
    const size_t base = (size_t)blockIdx.x * IN4;

    // Stage 1152 float4: 4 full rounds + 128-thread remainder
#pragma unroll
    for (int i = 0; i < 4; i++) {
        uint32_t dst = (uint32_t)__cvta_generic_to_shared(&s[i * TPB + tid]);
        const float4* src = in4 + base + i * TPB + tid;
        asm volatile("cp.async.cg.shared.global [%0], [%1], 16;"
                     :: "r"(dst), "l"(src) : "memory");
    }
    if (tid < IN4 - 4 * TPB) {            // 128 threads
        uint32_t dst = (uint32_t)__cvta_generic_to_shared(&s[4 * TPB + tid]);
        const float4* src = in4 + base + 4 * TPB + tid;
        asm volatile("cp.async.cg.shared.global [%0], [%1], 16;"
                     :: "r"(dst), "l"(src) : "memory");
    }
    asm volatile("cp.async.commit_group;" ::: "memory");
    asm volatile("cp.async.wait_group 0;" ::: "memory");
    __syncthreads();

    // 2 rows = 18 floats = 9 LDS.64 at 72B lane stride (conflict-free)
    float x[18];
#pragma unroll
    for (int k = 0; k < 9; k++) {
        float2 v = sf2[tid * 9 + k];
        x[2*k+0] = v.x; x[2*k+1] = v.y;
    }
    __syncthreads();                      // reads done before buffer reuse

    float o[6];
    process_row(x, o);
    process_row(x + 9, o + 3);

    // 6 floats = 3 STS.64 at 24B lane stride (conflict-free)
#pragma unroll
    for (int k = 0; k < 3; k++) {
        float2 v; v.x = o[2*k]; v.y = o[2*k+1];
        sf2[tid * 3 + k] = v;
    }
    __syncthreads();

    // Coalesced output: 384 float4 (256 + 128)
    const size_t obase = (size_t)blockIdx.x * OUT4;
    out4[obase + tid] = s[tid];
    if (tid < OUT4 - TPB)
        out4[obase + TPB + tid] = s[TPB + tid];
}

// Scalar tail for n_rows % 512 != 0 (not hit for N = 2^23)
__global__ void concat_tail(const float* __restrict__ in,
                            float* __restrict__ out,
                            int row_start, int n_rows)
{
    int row = row_start + blockIdx.x * blockDim.x + threadIdx.x;
    if (row >= n_rows) return;
    float x[9];
#pragma unroll
    for (int k = 0; k < 9; k++) x[k] = in[(size_t)row * 9 + k];
    float o[3];
    process_row(x, o);
#pragma unroll
    for (int k = 0; k < 3; k++) out[(size_t)row * 3 + k] = o[k];
}

extern "C" void kernel_launch(void* const* d_in, const int* in_sizes, int n_in,
                              void* d_out, int out_size)
{
    const float* in = (const float*)d_in[0];
    float* out = (float*)d_out;
    int n_rows = in_sizes[0] / 9;

    int nfull = n_rows / RPB;
    if (nfull > 0)
        concat_r2<<<nfull, TPB>>>((const float4*)in, (float4*)out);

    int done = nfull * RPB;
    int rem = n_rows - done;
    if (rem > 0) {
        int grid = (rem + 255) / 256;
        concat_tail<<<grid, 256>>>(in, out, done, n_rows);
    }
}